// round 1
// baseline (speedup 1.0000x reference)
#include <cuda_runtime.h>
#include <math.h>

#define Bc 2
#define Sc 2048
#define Ec 1024
#define NHc 4
#define DHc 256

// scratch (device globals: no allocation allowed)
__device__ float g_ig [Bc*NHc*Sc];
__device__ float g_lsf[Bc*NHc*Sc];
__device__ float g_m  [Bc*NHc*Sc];
__device__ float g_pm [Bc*NHc*Sc];
__device__ float g_mld[Bc*NHc*Sc];

// ---------------------------------------------------------------------------
// Kernel A: gate pre-activations.  ig/fg[b,s,h] = concat(q,k,v)[b,s,:] . w[h] + bias
// one warp per (b,s) row; 8 accumulators per lane; float4 loads.
// ---------------------------------------------------------------------------
__global__ __launch_bounds__(256) void gates_kernel(
    const float* __restrict__ q, const float* __restrict__ k, const float* __restrict__ v,
    const float* __restrict__ igw, const float* __restrict__ igb,
    const float* __restrict__ fgw, const float* __restrict__ fgb)
{
    int row  = blockIdx.x * 8 + (threadIdx.x >> 5);   // (b*S + s)
    int lane = threadIdx.x & 31;
    int b = row >> 11;
    int s = row & (Sc - 1);
    size_t off = (size_t)row * Ec;

    float aig[4] = {0.f,0.f,0.f,0.f};
    float afg[4] = {0.f,0.f,0.f,0.f};

    #pragma unroll
    for (int part = 0; part < 3; ++part) {
        const float* bp = (part == 0) ? (q + off) : (part == 1) ? (k + off) : (v + off);
        #pragma unroll
        for (int it = 0; it < 8; ++it) {
            int f = it * 128 + lane * 4;
            float4 x = *(const float4*)(bp + f);
            int wf = part * 1024 + f;
            #pragma unroll
            for (int h = 0; h < 4; ++h) {
                float4 w = *(const float4*)(igw + h * 3072 + wf);
                aig[h] += x.x*w.x + x.y*w.y + x.z*w.z + x.w*w.w;
                float4 g = *(const float4*)(fgw + h * 3072 + wf);
                afg[h] += x.x*g.x + x.y*g.y + x.z*g.z + x.w*g.w;
            }
        }
    }
    #pragma unroll
    for (int o = 16; o; o >>= 1) {
        #pragma unroll
        for (int h = 0; h < 4; ++h) {
            aig[h] += __shfl_xor_sync(0xffffffffu, aig[h], o);
            afg[h] += __shfl_xor_sync(0xffffffffu, afg[h], o);
        }
    }
    if (lane < 4) {
        float val = (lane==0?aig[0]:lane==1?aig[1]:lane==2?aig[2]:aig[3]) + igb[lane];
        g_ig[(b * NHc + lane) * Sc + s] = val;
    } else if (lane < 8) {
        int h = lane - 4;
        float fgv = (h==0?afg[0]:h==1?afg[1]:h==2?afg[2]:afg[3]) + fgb[h];
        // log_sigmoid, numerically stable
        float lsf = fminf(fgv, 0.f) - log1pf(expf(-fabsf(fgv)));
        g_lsf[(b * NHc + h) * Sc + s] = lsf;
    }
}

// ---------------------------------------------------------------------------
// Kernel B: per (b,h): cs = cumsum(lsf); m[j] = ig[j] - cs[j-1];
//           pm = prefix-max(m); mld[i] = cs[i] + pm[i]
// Hillis-Steele scans over S=2048 with 1024 threads.
// ---------------------------------------------------------------------------
__global__ __launch_bounds__(1024) void scan_kernel()
{
    __shared__ float s_a[2048];
    __shared__ float s_b[2048];
    __shared__ float s_cs[2048];

    int bh = blockIdx.x;
    int t  = threadIdx.x;
    const int base = bh * Sc;

    s_a[t]        = g_lsf[base + t];
    s_a[t + 1024] = g_lsf[base + t + 1024];
    __syncthreads();

    float* src = s_a; float* dst = s_b;
    for (int off = 1; off < 2048; off <<= 1) {
        #pragma unroll
        for (int u = 0; u < 2; ++u) {
            int i = t + (u << 10);
            float val = src[i];
            if (i >= off) val += src[i - off];
            dst[i] = val;
        }
        __syncthreads();
        float* tmp = src; src = dst; dst = tmp;
    }
    s_cs[t]        = src[t];
    s_cs[t + 1024] = src[t + 1024];
    __syncthreads();

    #pragma unroll
    for (int u = 0; u < 2; ++u) {
        int i = t + (u << 10);
        float m = g_ig[base + i] - (i > 0 ? s_cs[i - 1] : 0.f);
        g_m[base + i] = m;
        s_a[i] = m;
    }
    __syncthreads();

    src = s_a; dst = s_b;
    for (int off = 1; off < 2048; off <<= 1) {
        #pragma unroll
        for (int u = 0; u < 2; ++u) {
            int i = t + (u << 10);
            float val = src[i];
            if (i >= off) val = fmaxf(val, src[i - off]);
            dst[i] = val;
        }
        __syncthreads();
        float* tmp = src; src = dst; dst = tmp;
    }
    #pragma unroll
    for (int u = 0; u < 2; ++u) {
        int i = t + (u << 10);
        g_pm[base + i]  = src[i];
        g_mld[base + i] = s_cs[i] + src[i];
    }
}

// ---------------------------------------------------------------------------
// Kernel C: tiled causal "attention": per (b,h) and 64-row tile,
//   P[i,j] = (q_i . k_j)/16 * exp(m[j]-pm[i])  (j<=i)
//   h[i]   = (sum_j P[i,j] v_j) / (max(|sum_j P[i,j]|, exp(-mld[i])) + 1e-8)
//   then per-head LayerNorm with scale (1+out_w).
// blocks: 128 = 8 (b,h) * 16 pairs; each block does row tiles {p, 31-p}.
// ---------------------------------------------------------------------------
#define SM_QS   0
#define SM_KS   16640
#define SM_PS   (16640 + 4096)
#define SM_VS   (16640 + 4096 + 4352)
#define SM_RS   (16640 + 4096 + 4352 + 4096)
#define SM_FLOATS (16640 + 4096 + 4352 + 4096 + 192)
#define SMEM_BYTES (SM_FLOATS * 4)

__global__ __launch_bounds__(256, 1) void attn_kernel(
    const float* __restrict__ q, const float* __restrict__ k,
    const float* __restrict__ v, const float* __restrict__ out_w,
    float* __restrict__ out)
{
    extern __shared__ float sm[];
    float* Qs     = sm + SM_QS;    // QK phase: Qs[d*64 + r] (d=0..255). Epilogue: H[r*260 + c]
    float* Ks     = sm + SM_KS;    // Ks[dd*64 + c], dd in chunk of 64
    float* Ps     = sm + SM_PS;    // Ps[r*68 + j]
    float* Vs     = sm + SM_VS;    // Vs[j*64 + cl]
    float* rowsum = sm + SM_RS;    // [64]
    float* rowpm  = rowsum + 64;   // [64]
    float* rowmld = rowpm + 64;    // [64]

    const int tid  = threadIdx.x;
    const int bh   = blockIdx.x >> 4;
    const int pair = blockIdx.x & 15;
    const int b = bh >> 2, h = bh & 3;

    const size_t hb = (size_t)h * DHc;
    const float* qB = q + (size_t)b * Sc * Ec + hb;
    const float* kB = k + (size_t)b * Sc * Ec + hb;
    const float* vB = v + (size_t)b * Sc * Ec + hb;
    const float* mArr = g_m + bh * Sc;

    const int ty  = tid >> 4, tx  = tid & 15;   // QK phase: 16x16, 4x4 micro-tile
    const int ty2 = tid >> 5, tx2 = tid & 31;   // PV phase: 8x32, 8 rows x 8 cols

    for (int which = 0; which < 2; ++which) {
        const int rt = which ? (31 - pair) : pair;
        const int r0 = rt * 64;

        // ---- load Q tile transposed: Qs[d][r] ----
        {
            int r  = tid & 63;
            int dq = (tid >> 6) << 6;            // 0,64,128,192
            const float* src = qB + (size_t)(r0 + r) * Ec + dq;
            #pragma unroll
            for (int i = 0; i < 16; ++i) {
                float4 x = *(const float4*)(src + i * 4);
                int d = dq + i * 4;
                Qs[(d+0)*64 + r] = x.x;
                Qs[(d+1)*64 + r] = x.y;
                Qs[(d+2)*64 + r] = x.z;
                Qs[(d+3)*64 + r] = x.w;
            }
            if (tid < 64) {
                rowsum[tid] = 0.f;
                rowpm [tid] = g_pm [bh * Sc + r0 + tid];
                rowmld[tid] = g_mld[bh * Sc + r0 + tid];
            }
        }

        float o[8][8];
        #pragma unroll
        for (int a = 0; a < 8; ++a)
            #pragma unroll
            for (int c = 0; c < 8; ++c) o[a][c] = 0.f;

        __syncthreads();

        for (int jt = 0; jt <= rt; ++jt) {
            const int t0 = jt * 64;

            // ---------------- QK^T: 64x64 tile ----------------
            float p[4][4];
            #pragma unroll
            for (int i = 0; i < 4; ++i)
                #pragma unroll
                for (int j = 0; j < 4; ++j) p[i][j] = 0.f;

            for (int ch = 0; ch < 4; ++ch) {
                { // load K chunk transposed: Ks[dd][c]
                    int c  = tid & 63;
                    int db = (tid >> 6) << 4;    // 0,16,32,48
                    const float* src = kB + (size_t)(t0 + c) * Ec + ch * 64 + db;
                    #pragma unroll
                    for (int i = 0; i < 4; ++i) {
                        float4 x = *(const float4*)(src + i * 4);
                        int dd = db + i * 4;
                        Ks[(dd+0)*64 + c] = x.x;
                        Ks[(dd+1)*64 + c] = x.y;
                        Ks[(dd+2)*64 + c] = x.z;
                        Ks[(dd+3)*64 + c] = x.w;
                    }
                }
                __syncthreads();
                const float* Qc = Qs + (ch << 6) * 64;
                #pragma unroll 8
                for (int dd = 0; dd < 64; ++dd) {
                    float4 a  = *(const float4*)(Qc + dd * 64 + 4 * ty);
                    float4 bb = *(const float4*)(Ks + dd * 64 + 4 * tx);
                    p[0][0] += a.x*bb.x; p[0][1] += a.x*bb.y; p[0][2] += a.x*bb.z; p[0][3] += a.x*bb.w;
                    p[1][0] += a.y*bb.x; p[1][1] += a.y*bb.y; p[1][2] += a.y*bb.z; p[1][3] += a.y*bb.w;
                    p[2][0] += a.z*bb.x; p[2][1] += a.z*bb.y; p[2][2] += a.z*bb.z; p[2][3] += a.z*bb.w;
                    p[3][0] += a.w*bb.x; p[3][1] += a.w*bb.y; p[3][2] += a.w*bb.z; p[3][3] += a.w*bb.w;
                }
                __syncthreads();
            }

            // ---------------- decay * mask + row sums + store P ----------------
            {
                float mj[4];
                #pragma unroll
                for (int j = 0; j < 4; ++j) mj[j] = mArr[t0 + 4 * tx + j];

                float rsum[4];
                #pragma unroll
                for (int i = 0; i < 4; ++i) {
                    int gr = r0 + 4 * ty + i;
                    float pmv = rowpm[4 * ty + i];
                    float rs = 0.f;
                    #pragma unroll
                    for (int j = 0; j < 4; ++j) {
                        int gc = t0 + 4 * tx + j;
                        float val = (gc <= gr) ? p[i][j] * 0.0625f * __expf(mj[j] - pmv) : 0.f;
                        p[i][j] = val;
                        rs += val;
                    }
                    rsum[i] = rs;
                }
                #pragma unroll
                for (int off = 8; off; off >>= 1) {
                    #pragma unroll
                    for (int i = 0; i < 4; ++i)
                        rsum[i] += __shfl_xor_sync(0xffffffffu, rsum[i], off);
                }
                if (tx == 0) {
                    #pragma unroll
                    for (int i = 0; i < 4; ++i) rowsum[4 * ty + i] += rsum[i];
                }
                #pragma unroll
                for (int i = 0; i < 4; ++i)
                    *(float4*)(Ps + (4 * ty + i) * 68 + 4 * tx) =
                        make_float4(p[i][0], p[i][1], p[i][2], p[i][3]);
                __syncthreads();
            }

            // ---------------- P @ V ----------------
            #pragma unroll
            for (int cchunk = 0; cchunk < 4; ++cchunk) {
                { // load V chunk: Vs[j][cl]
                    #pragma unroll
                    for (int u = 0; u < 4; ++u) {
                        int lin = tid + u * 256;
                        int j   = lin >> 4;
                        int c4  = (lin & 15) << 2;
                        float4 x = *(const float4*)(vB + (size_t)(t0 + j) * Ec + cchunk * 64 + c4);
                        *(float4*)(Vs + j * 64 + c4) = x;
                    }
                }
                __syncthreads();
                #pragma unroll 2
                for (int jg = 0; jg < 16; ++jg) {
                    float4 pv[8];
                    #pragma unroll
                    for (int rr = 0; rr < 8; ++rr)
                        pv[rr] = *(const float4*)(Ps + (ty2 + 8 * rr) * 68 + 4 * jg);
                    #pragma unroll
                    for (int jj = 0; jj < 4; ++jj) {
                        float v0 = Vs[(4 * jg + jj) * 64 + tx2];
                        float v1 = Vs[(4 * jg + jj) * 64 + tx2 + 32];
                        #pragma unroll
                        for (int rr = 0; rr < 8; ++rr) {
                            float pj = (jj == 0) ? pv[rr].x : (jj == 1) ? pv[rr].y
                                     : (jj == 2) ? pv[rr].z : pv[rr].w;
                            o[rr][2 * cchunk]     += pj * v0;
                            o[rr][2 * cchunk + 1] += pj * v1;
                        }
                    }
                }
                __syncthreads();
            }
        } // jt

        // ---------------- epilogue: normalize rows, write H, LayerNorm ----------------
        {
            float inv[8];
            #pragma unroll
            for (int rr = 0; rr < 8; ++rr) {
                int r = ty2 + 8 * rr;
                float nrm = fmaxf(fabsf(rowsum[r]), expf(-rowmld[r])) + 1e-8f;
                inv[rr] = 1.f / nrm;
            }
            #pragma unroll
            for (int rr = 0; rr < 8; ++rr)
                #pragma unroll
                for (int cc = 0; cc < 8; ++cc)
                    Qs[(ty2 + 8 * rr) * 260 + tx2 + 32 * cc] = o[rr][cc] * inv[rr];
        }
        __syncthreads();
        {
            int r  = tid >> 2;
            int qd = tid & 3;
            const float* hrow = Qs + r * 260 + qd * 64;
            float s1 = 0.f;
            #pragma unroll
            for (int i = 0; i < 16; ++i) {
                float4 x = *(const float4*)(hrow + i * 4);
                s1 += x.x + x.y + x.z + x.w;
            }
            s1 += __shfl_xor_sync(0xffffffffu, s1, 1);
            s1 += __shfl_xor_sync(0xffffffffu, s1, 2);
            float mean = s1 * (1.f / 256.f);
            float s2 = 0.f;
            #pragma unroll
            for (int i = 0; i < 16; ++i) {
                float4 x = *(const float4*)(hrow + i * 4);
                float d0 = x.x - mean, d1 = x.y - mean, d2 = x.z - mean, d3 = x.w - mean;
                s2 += d0*d0 + d1*d1 + d2*d2 + d3*d3;
            }
            s2 += __shfl_xor_sync(0xffffffffu, s2, 1);
            s2 += __shfl_xor_sync(0xffffffffu, s2, 2);
            float rstd = rsqrtf(s2 * (1.f / 256.f) + 1e-5f);

            float* dst = out + ((size_t)b * Sc + r0 + r) * Ec + hb + qd * 64;
            const float* ow = out_w + hb + qd * 64;
            #pragma unroll
            for (int i = 0; i < 16; ++i) {
                float4 x = *(const float4*)(hrow + i * 4);
                float4 w = *(const float4*)(ow + i * 4);
                float4 y;
                y.x = (x.x - mean) * rstd * (1.f + w.x);
                y.y = (x.y - mean) * rstd * (1.f + w.y);
                y.z = (x.z - mean) * rstd * (1.f + w.z);
                y.w = (x.w - mean) * rstd * (1.f + w.w);
                *(float4*)(dst + i * 4) = y;
            }
        }
        __syncthreads();
    } // which
}

// ---------------------------------------------------------------------------
extern "C" void kernel_launch(void* const* d_in, const int* in_sizes, int n_in,
                              void* d_out, int out_size)
{
    const float* q   = (const float*)d_in[0];
    const float* k   = (const float*)d_in[1];
    const float* v   = (const float*)d_in[2];
    const float* igw = (const float*)d_in[3];
    const float* igb = (const float*)d_in[4];
    const float* fgw = (const float*)d_in[5];
    const float* fgb = (const float*)d_in[6];
    const float* ow  = (const float*)d_in[7];
    float* out = (float*)d_out;

    cudaFuncSetAttribute(attn_kernel, cudaFuncAttributeMaxDynamicSharedMemorySize, SMEM_BYTES);

    gates_kernel<<<(Bc * Sc) / 8, 256>>>(q, k, v, igw, igb, fgw, fgb);
    scan_kernel<<<Bc * NHc, 1024>>>();
    attn_kernel<<<(Bc * NHc) * 16, 256, SMEM_BYTES>>>(q, k, v, ow, out);
}